// round 9
// baseline (speedup 1.0000x reference)
#include <cuda_runtime.h>
#include <cstdint>

#define S_LEN 2048
#define BATCH 32
#define IDIM  256
#define HDIM  512
#define CL    8            // cluster size
#define THREADS_R 256

typedef unsigned long long ull;

// ---------------- PTX helpers ----------------
__device__ __forceinline__ ull pack2(float x, float y) {
    ull r; asm("mov.b64 %0, {%1, %2};" : "=l"(r) : "f"(x), "f"(y)); return r;
}
__device__ __forceinline__ void unpack2(ull v, float &x, float &y) {
    asm("mov.b64 {%0, %1}, %2;" : "=f"(x), "=f"(y) : "l"(v));
}
__device__ __forceinline__ void ffma2(ull &d, ull a, ull b) {
    asm("fma.rn.f32x2 %0, %1, %2, %0;" : "+l"(d) : "l"(a), "l"(b));
}
__device__ __forceinline__ uint32_t smem_u32(const void* p) {
    return (uint32_t)__cvta_generic_to_shared(p);
}
__device__ __forceinline__ uint32_t mapa_addr(uint32_t laddr, uint32_t rank) {
    uint32_t raddr;
    asm("mapa.shared::cluster.u32 %0, %1, %2;" : "=r"(raddr) : "r"(laddr), "r"(rank));
    return raddr;
}
// bulk smem->remote-smem copy, completes on remote mbarrier (tx bytes)
__device__ __forceinline__ void bulk_s2s(uint32_t dst, uint32_t src, uint32_t bytes, uint32_t rmbar) {
    asm volatile("cp.async.bulk.shared::cluster.shared::cta.mbarrier::complete_tx::bytes "
                 "[%0], [%1], %2, [%3];"
                 :: "r"(dst), "r"(src), "r"(bytes), "r"(rmbar) : "memory");
}
__device__ __forceinline__ void fence_async_() {
    asm volatile("fence.proxy.async.shared::cta;" ::: "memory");
}
__device__ __forceinline__ void mbar_init(uint32_t mbar, uint32_t cnt) {
    asm volatile("mbarrier.init.shared.b64 [%0], %1;" :: "r"(mbar), "r"(cnt) : "memory");
}
__device__ __forceinline__ void mbar_arm(uint32_t mbar, uint32_t tx) {
    asm volatile("mbarrier.arrive.expect_tx.shared.b64 _, [%0], %1;" :: "r"(mbar), "r"(tx) : "memory");
}
__device__ __forceinline__ void mbar_wait(uint32_t mbar, uint32_t parity) {
    uint32_t done;
    asm volatile("{\n\t.reg .pred p;\n\t"
                 "mbarrier.try_wait.parity.acquire.cta.shared::cta.b64 p, [%1], %2;\n\t"
                 "selp.b32 %0, 1, 0, p;\n\t}"
                 : "=r"(done) : "r"(mbar), "r"(parity) : "memory");
    if (!done) {
        asm volatile("{\n\t.reg .pred P1;\n\t"
                     "WL%=:\n\t"
                     "mbarrier.try_wait.parity.acquire.cta.shared::cta.b64 P1, [%0], %1, 0x989680;\n\t"
                     "@P1 bra.uni WD%=;\n\t"
                     "bra.uni WL%=;\n\t"
                     "WD%=:\n\t}"
                     :: "r"(mbar), "r"(parity) : "memory");
    }
}
__device__ __forceinline__ void cluster_sync_() {
    asm volatile("barrier.cluster.arrive.aligned;" ::: "memory");
    asm volatile("barrier.cluster.wait.aligned;"   ::: "memory");
}

// =====================================================================
// Phase 1: z = inputs @ Wih^T + (bih + bhh), in-place into d_out.
// Packed f32x2 inner product (pairs along N) -> 2x fma-pipe throughput.
// =====================================================================
#define BM 64
#define BN 64
#define BK 32

__global__ __launch_bounds__(256) void zproj_kernel(
    const float* __restrict__ A, const float* __restrict__ W,
    const float* __restrict__ bih, const float* __restrict__ bhh,
    float* __restrict__ C)
{
    __shared__ __align__(16) float As[BK][BM + 8];
    __shared__ __align__(16) float Bs[BK][BN + 8];
    const int tid = threadIdx.x;
    const int m0 = blockIdx.x * BM;
    const int n0 = blockIdx.y * BN;
    const int tx = tid & 15;
    const int ty = tid >> 4;
    ull acc01[4] = {0,0,0,0};   // [i] -> {acc[i][0], acc[i][1]}
    ull acc23[4] = {0,0,0,0};   // [i] -> {acc[i][2], acc[i][3]}

    for (int k0 = 0; k0 < IDIM; k0 += BK) {
        #pragma unroll
        for (int i = 0; i < 2; i++) {
            int s  = tid + i * 256;
            int m  = s >> 3;
            int kq = (s & 7) << 2;
            float4 a = *(const float4*)(A + (size_t)(m0 + m) * IDIM + k0 + kq);
            As[kq+0][m] = a.x; As[kq+1][m] = a.y; As[kq+2][m] = a.z; As[kq+3][m] = a.w;
            float4 b = *(const float4*)(W + (size_t)(n0 + m) * IDIM + k0 + kq);
            Bs[kq+0][m] = b.x; Bs[kq+1][m] = b.y; Bs[kq+2][m] = b.z; Bs[kq+3][m] = b.w;
        }
        __syncthreads();
        #pragma unroll
        for (int k = 0; k < BK; k++) {
            float4 a4 = *(const float4*)&As[k][ty * 4];
            const ull* bp = (const ull*)&Bs[k][tx * 4];
            ull b01 = bp[0], b23 = bp[1];
            ull a0 = pack2(a4.x, a4.x);
            ull a1 = pack2(a4.y, a4.y);
            ull a2 = pack2(a4.z, a4.z);
            ull a3 = pack2(a4.w, a4.w);
            ffma2(acc01[0], a0, b01); ffma2(acc23[0], a0, b23);
            ffma2(acc01[1], a1, b01); ffma2(acc23[1], a1, b23);
            ffma2(acc01[2], a2, b01); ffma2(acc23[2], a2, b23);
            ffma2(acc01[3], a3, b01); ffma2(acc23[3], a3, b23);
        }
        __syncthreads();
    }

    float bias[4];
    #pragma unroll
    for (int j = 0; j < 4; j++)
        bias[j] = bih[n0 + tx * 4 + j] + bhh[n0 + tx * 4 + j];

    #pragma unroll
    for (int i = 0; i < 4; i++) {
        float4 o;
        unpack2(acc01[i], o.x, o.y);
        unpack2(acc23[i], o.z, o.w);
        o.x += bias[0]; o.y += bias[1]; o.z += bias[2]; o.w += bias[3];
        *(float4*)(C + (size_t)(m0 + ty * 4 + i) * HDIM + n0 + tx * 4) = o;
    }
}

// =====================================================================
// Phase 2: persistent cluster scan with AGGREGATED bulk DSMEM exchange.
// 16 clusters x 8 CTAs; cluster owns 2 batches; CTA rank r owns h rows
// [64r, 64r+64); W slice in registers (k-pair packed f32x2).
// h buffer layout: 2 bufs x 8 rank-blocks x 132 floats (512B data +
// 16B pad -> conflict-free LDS across the 8 k-chunk lanes).
// Per step: matvec -> shfl-bfly reduce -> pushers stage 512B locally ->
// __syncthreads -> ONE thread issues 8x cp.async.bulk (512B) to the
// cluster, each completing on the destination's mbarrier (tx=4096).
// 8 mbarrier updates/CTA/step instead of 512 st.async.
// =====================================================================
#define TX_PER_STEP 4096u   // 8 ranks * 512B

__global__ void __cluster_dims__(CL, 1, 1) __launch_bounds__(THREADS_R, 1)
rnn_scan_kernel(const float* __restrict__ Whh,
                const float* __restrict__ h0,
                float* __restrict__ out)
{
    __shared__ __align__(16) float hs[2][8][132];   // [buf][rank-block][b0:0..63 | b1:64..127 | pad]
    __shared__ __align__(16) float stage[2][128];   // [buf][b0 rows 0..63 | b1 rows 0..63]
    __shared__ __align__(8)  ull mbarS[2];

    const int tid = threadIdx.x;
    const int w   = tid >> 5;
    const int l   = tid & 31;
    const int kc  = l & 7;               // k-chunk 0..7 (64 k's each)
    const int rp4 = l >> 3;
    const int rpL = w * 4 + rp4;         // CTA-local rowpair 0..31
    uint32_t rank; asm("mov.u32 %0, %%cluster_ctarank;" : "=r"(rank));
    const int b0 = (blockIdx.x / CL) * 2;

    const uint32_t m0a = smem_u32(&mbarS[0]);
    const uint32_t hsu = smem_u32(&hs[0][0][0]);
    const uint32_t stu = smem_u32(&stage[0][0]);

    // ---- W slice into regs: rows {2rpL, 2rpL+1}, k in [kc*64, kc*64+64) ----
    const int grow = (int)rank * 64 + 2 * rpL;
    const ull* wr0 = (const ull*)(Whh + (size_t)grow * HDIM + kc * 64);
    const ull* wr1 = wr0 + (HDIM / 2);
    ull w2a[32], w2b[32];
    #pragma unroll
    for (int j = 0; j < 32; j++) { w2a[j] = wr0[j]; w2b[j] = wr1[j]; }

    // ---- init h buffer 0 from h0 ----
    for (int g = tid; g < HDIM; g += THREADS_R) {
        hs[0][g >> 6][g & 63]        = h0[(size_t)b0 * HDIM + g];
        hs[0][g >> 6][64 + (g & 63)] = h0[(size_t)(b0 + 1) * HDIM + g];
    }
    if (tid == 0) {
        mbar_init(m0a, 1);
        mbar_init(m0a + 8, 1);
        mbar_arm(m0a, TX_PER_STEP);       // buf0: filled during step 1, waited at t=2
        mbar_arm(m0a + 8, TX_PER_STEP);   // buf1: filled during step 0, waited at t=1
    }
    __syncthreads();
    cluster_sync_();   // all CTAs: h0 + armed mbarriers visible before any bulk copy

    // ---- sender precompute (tid 0) ----
    uint32_t rb[8];
    uint32_t mbdelta = m0a - hsu;
    #pragma unroll
    for (uint32_t r = 0; r < CL; r++) rb[r] = mapa_addr(hsu, r);
    const uint32_t myblk = rank * 528u;   // byte offset of this rank's block within a buffer

    // ---- pusher identity (lanes kc<2: batch=kc, rows {2rpL, 2rpL+1}) ----
    const bool pusher = (kc < 2);
    const int pb = kc;
    size_t zoff = 0, foff = 0;
    float2 z_cur = make_float2(0.f, 0.f);
    if (pusher) {
        zoff = ((size_t)(b0 + pb) * S_LEN) * HDIM + grow;
        foff = (size_t)BATCH * S_LEN * HDIM + (size_t)(b0 + pb) * HDIM + grow;
        z_cur = *(const float2*)(out + zoff);   // z[t=0] prefetch
    }

    int cur = 0;
    uint32_t p0 = 0, p1 = 0;
    for (int t = 0; t < S_LEN; t++) {
        // prefetch z_{t+1} before the wait (last iter reads in-bounds scratch)
        float2 z_next = z_cur;
        if (pusher) z_next = *(const float2*)(out + zoff + HDIM);

        if (t > 0) {
            if (cur) { mbar_wait(m0a + 8, p1); p1 ^= 1; }
            else     { mbar_wait(m0a,     p0); p0 ^= 1; }
            if (tid == 0) mbar_arm(cur ? (m0a + 8) : m0a, TX_PER_STEP); // refill during t+1
        }

        // ---- register matvec over this thread's 64 k's ----
        const ull* hb0 = (const ull*)&hs[cur][kc][0];    // batch0: 32 k-pairs
        const ull* hb1 = hb0 + 32;                       // batch1
        ull aA0 = 0, aA1 = 0, aB0 = 0, aB1 = 0;
        #pragma unroll
        for (int j = 0; j < 32; j++) {
            ull h0v = hb0[j];
            ull h1v = hb1[j];
            ffma2(aA0, w2a[j], h0v);   // row0, batch0
            ffma2(aA1, w2b[j], h0v);   // row1, batch0
            ffma2(aB0, w2a[j], h1v);   // row0, batch1
            ffma2(aB1, w2b[j], h1v);   // row1, batch1
        }
        float x, y, s0, s1, s2, s3;
        unpack2(aA0, x, y); s0 = x + y;
        unpack2(aA1, x, y); s1 = x + y;
        unpack2(aB0, x, y); s2 = x + y;
        unpack2(aB1, x, y); s3 = x + y;

        // ---- butterfly reduce across the 8 kc lanes ----
        #pragma unroll
        for (int m = 1; m < 8; m <<= 1) {
            s0 += __shfl_xor_sync(0xffffffffu, s0, m);
            s1 += __shfl_xor_sync(0xffffffffu, s1, m);
            s2 += __shfl_xor_sync(0xffffffffu, s2, m);
            s3 += __shfl_xor_sync(0xffffffffu, s3, m);
        }

        if (pusher) {
            float a = (kc == 0) ? s0 : s2;
            float b = (kc == 0) ? s1 : s3;
            float v0 = fmaxf(z_cur.x + a, 0.f);
            float v1 = fmaxf(z_cur.y + b, 0.f);
            ((float2*)&stage[cur][0])[pb * 32 + rpL] = make_float2(v0, v1);
            *(float2*)(out + zoff) = make_float2(v0, v1);   // h_t overwrites z_t
            if (t == S_LEN - 1)
                *(float2*)(out + foff) = make_float2(v0, v1);
            z_cur = z_next;
            zoff += HDIM;
        }
        __syncthreads();   // stage complete (BAR drains STS)

        if (tid == 0 && t < S_LEN - 1) {
            fence_async_();                      // generic STS -> async-proxy read
            const int nxt = cur ^ 1;
            uint32_t doff = (uint32_t)nxt * 4224u + myblk;
            uint32_t moff = mbdelta + (uint32_t)nxt * 8u;
            uint32_t src  = stu + (uint32_t)cur * 512u;
            #pragma unroll
            for (int r = 0; r < CL; r++)
                bulk_s2s(rb[r] + doff, src, 512u, rb[r] + moff);
        }
        cur ^= 1;
    }
}

// =====================================================================
extern "C" void kernel_launch(void* const* d_in, const int* in_sizes, int n_in,
                              void* d_out, int out_size) {
    (void)in_sizes; (void)n_in; (void)out_size;
    const float* inputs = (const float*)d_in[0];
    const float* h0     = (const float*)d_in[1];
    const float* Wih    = (const float*)d_in[2];
    const float* Whh    = (const float*)d_in[3];
    const float* bih    = (const float*)d_in[4];
    const float* bhh    = (const float*)d_in[5];
    float* out = (float*)d_out;

    dim3 g1((BATCH * S_LEN) / BM, HDIM / BN);
    zproj_kernel<<<g1, 256>>>(inputs, Wih, bih, bhh, out);
    rnn_scan_kernel<<<(BATCH / 2) * CL, THREADS_R>>>(Whh, h0, out);
}